// round 15
// baseline (speedup 1.0000x reference)
#include <cuda_runtime.h>
#include <math.h>

// ---------------------------------------------------------------------------
// MS-SSIM, 5 levels, [16,3,512,512] f32.  (R15: 2-kernel pipeline)
//   0) memsetAsync g_sums = 0
//   1) fused kernel, 15360 blocks:
//        bid <  3072 : pyramid blocks — build L1..L4 from L0 (DRAM-bound,
//                      overlaps with ssim compute)
//        bid >= 3072 : L0 ssim tiles (no pool — pyramid handles L1)
//   2) ssim_rest (4080 blk, levels 1-4) + finalize folded into last block
// Tile core: u=x+y / v=x-y, separable 11-tap blur, k-outer, XOR swizzles.
// ---------------------------------------------------------------------------

#define NPLANES 48
#define HALO 5
#define TW 32
#define TH 32
#define INW 42
#define INWP 44        // float2 units per row (352B)
#define INH 42
#define NT 256

#define G0 0.001028380f
#define G1 0.007598758f
#define G2 0.036000770f
#define G3 0.109360700f
#define G4 0.213005550f
#define G5 0.266011740f

__device__ __forceinline__ float gw(int k) {
    switch (k) {
        case 0: case 10: return G0;
        case 1: case 9:  return G1;
        case 2: case 8:  return G2;
        case 3: case 7:  return G3;
        case 4: case 6:  return G4;
        default:         return G5;
    }
}

__device__ __forceinline__ int swzg(int g) { return g ^ ((g >> 3) & 1); }
__device__ __forceinline__ int suv_idx(int r, int c) {
    int g = swzg(c >> 1);
    return r * INWP + (g << 1) + (c & 1);
}
__device__ __forceinline__ int swzc(int col) { return col ^ (col >> 2); }

#define C1F 0.0001f
#define C2F 0.0009f

__device__ double g_sums[10];
__device__ unsigned int g_done = 0;

#define OFF_L1 0
#define OFF_L2 3145728
#define OFF_L3 3932160
#define OFF_L4 4128768
#define SCR_TOTAL 4177920
__device__ float g_scr1[SCR_TOTAL];
__device__ float g_scr2[SCR_TOTAL];

// ---------------------------------------------------------------------------
// Shared ssim tile routine (no pool)
// ---------------------------------------------------------------------------
__device__ __forceinline__ void ssim_tile(
    const float* __restrict__ p1, const float* __restrict__ p2,
    int x0, int y0, int H, int W, int level,
    float2* s_uv, float4* h4, float* red_s, float* red_c)
{
    const int t = threadIdx.x;

    const bool interior = (x0 >= HALO) && (y0 >= HALO) &&
                          (x0 + TW + HALO <= W) && (y0 + TH + HALO <= H);
    if (interior) {
        #pragma unroll
        for (int i = 0; i < 7; i++) {
            int idx = t + i * NT;
            if (idx < INH * INW) {
                int r = idx / INW, c = idx - r * INW;
                int gi = (y0 + r - HALO) * W + (x0 + c - HALO);
                float a = __ldg(p1 + gi);
                float b = __ldg(p2 + gi);
                s_uv[suv_idx(r, c)] = make_float2(a + b, a - b);
            }
        }
    } else {
        #pragma unroll
        for (int i = 0; i < 7; i++) {
            int idx = t + i * NT;
            if (idx < INH * INW) {
                int r = idx / INW, c = idx - r * INW;
                int gy = y0 + r - HALO;
                int gx = x0 + c - HALO;
                float a = 0.f, b = 0.f;
                if (gy >= 0 && gy < H && gx >= 0 && gx < W) {
                    int gi = gy * W + gx;
                    a = __ldg(p1 + gi);
                    b = __ldg(p2 + gi);
                }
                s_uv[suv_idx(r, c)] = make_float2(a + b, a - b);
            }
        }
    }
    __syncthreads();

    // horizontal pass: 42 rows x 8 groups of 4 cols = 336 tasks
    for (int task = t; task < INH * 8; task += NT) {
        const int r     = task >> 3;
        const int jgrp  = task & 7;
        const int cc    = jgrp << 2;
        const int gbase = jgrp << 1;
        const float4* s_uv4 = (const float4*)s_uv;
        const int rowb = r * (INWP >> 1);

        float aU[4] = {0,0,0,0}, aV[4] = {0,0,0,0};
        float aP[4] = {0,0,0,0}, aQ[4] = {0,0,0,0};

        #pragma unroll
        for (int kk = 0; kk < 7; kk++) {
            float4 q = s_uv4[rowb + swzg(gbase + kk)];
            #pragma unroll
            for (int h = 0; h < 2; h++) {
                const int k = 2 * kk + h;
                float u = h ? q.z : q.x;
                float v = h ? q.w : q.y;
                float uu = u * u;
                float vv = v * v;
                #pragma unroll
                for (int j = 0; j < 4; j++) {
                    const int ki = k - j;
                    if (ki >= 0 && ki <= 10) {
                        const float w = gw(ki);
                        aU[j] = fmaf(w, u,  aU[j]);
                        aV[j] = fmaf(w, v,  aV[j]);
                        aP[j] = fmaf(w, uu, aP[j]);
                        aQ[j] = fmaf(w, vv, aQ[j]);
                    }
                }
            }
        }
        #pragma unroll
        for (int j = 0; j < 4; j++)
            h4[r * TW + ((cc + j) ^ jgrp)] = make_float4(aU[j], aV[j], aP[j], aQ[j]);
    }
    __syncthreads();

    // vertical pass + epilogue: 256 tasks, 4 output rows each
    float lssim = 0.f, lcs = 0.f;
    {
        const int tx  = t & 31;
        const int txs = swzc(tx);
        const int rbase = (t >> 5) * 4;

        float aU[4] = {0,0,0,0}, aV[4] = {0,0,0,0};
        float aP[4] = {0,0,0,0}, aQ[4] = {0,0,0,0};
        #pragma unroll
        for (int k = 0; k < 14; k++) {
            float4 hv = h4[(rbase + k) * TW + txs];
            #pragma unroll
            for (int j = 0; j < 4; j++) {
                const int ki = k - j;
                if (ki >= 0 && ki <= 10) {
                    const float w = gw(ki);
                    aU[j] = fmaf(w, hv.x, aU[j]);
                    aV[j] = fmaf(w, hv.y, aV[j]);
                    aP[j] = fmaf(w, hv.z, aP[j]);
                    aQ[j] = fmaf(w, hv.w, aQ[j]);
                }
            }
        }

        #pragma unroll
        for (int j = 0; j < 4; j++) {
            float A = aU[j] * aU[j];
            float B = aV[j] * aV[j];
            float P = aP[j], Q = aQ[j];
            float num_l = 0.5f * (A - B) + C1F;
            float den_l = 0.5f * (A + B) + C1F;
            float num_c = 0.5f * ((P - Q) - (A - B)) + C2F;
            float den_c = 0.5f * ((P + Q) - (A + B)) + C2F;
            float cs = __fdividef(num_c, den_c);
            lssim += __fdividef(num_l, den_l) * cs;
            lcs   += cs;
        }

        #pragma unroll
        for (int o = 16; o > 0; o >>= 1) {
            lssim += __shfl_xor_sync(0xFFFFFFFFu, lssim, o);
            lcs   += __shfl_xor_sync(0xFFFFFFFFu, lcs,   o);
        }
        if (tx == 0) { red_s[t >> 5] = lssim; red_c[t >> 5] = lcs; }
    }
    __syncthreads();
    if (t == 0) {
        float S = 0.f, Cc = 0.f;
        #pragma unroll
        for (int i = 0; i < NT / 32; i++) { S += red_s[i]; Cc += red_c[i]; }
        atomicAdd(&g_sums[2 * level],     (double)S);
        atomicAdd(&g_sums[2 * level + 1], (double)Cc);
    }
}

// ---------------------------------------------------------------------------
// Launch 1: flat 15360 blocks.
//   bid < 3072  : pyramid block (64x64 L0 region -> L1..L4, both images)
//   bid >= 3072 : L0 ssim tile
// ---------------------------------------------------------------------------
__global__ void __launch_bounds__(NT, 6)
fused_l0_kernel(const float* __restrict__ img1, const float* __restrict__ img2,
                float* __restrict__ a1, float* __restrict__ b1,
                float* __restrict__ a2, float* __restrict__ b2,
                float* __restrict__ a3, float* __restrict__ b3,
                float* __restrict__ a4, float* __restrict__ b4)
{
    __shared__ __align__(16) float2 s_uv[INH * INWP];
    __shared__ __align__(16) float4 h4[INH * TW];
    __shared__ float red_s[NT / 32], red_c[NT / 32];

    const int bid = blockIdx.x;
    const int t = threadIdx.x;

    if (bid < 3072) {
        // ---- pyramid block ----
        float* sm2 = (float*)s_uv;           // 2*256 floats
        float* sm3 = (float*)s_uv + 512;     // 2*64 floats

        const int plane = bid >> 6;
        const int rem = bid & 63;
        const int x0 = (rem & 7) * 64, y0 = (rem >> 3) * 64;
        const int i = t >> 4, j = t & 15;

        #pragma unroll
        for (int img = 0; img < 2; img++) {
            const float* p = (img ? img2 : img1) + (size_t)plane * 512 * 512;
            float* d1 = (img ? b1 : a1) + (size_t)plane * 256 * 256;
            float* d2 = (img ? b2 : a2) + (size_t)plane * 128 * 128;

            const int ry = y0 + 4 * i;
            const int cx = x0 + 4 * j;
            float4 q0 = *(const float4*)(p + (size_t)(ry + 0) * 512 + cx);
            float4 q1 = *(const float4*)(p + (size_t)(ry + 1) * 512 + cx);
            float4 q2 = *(const float4*)(p + (size_t)(ry + 2) * 512 + cx);
            float4 q3 = *(const float4*)(p + (size_t)(ry + 3) * 512 + cx);

            float l00 = 0.25f * ((q0.x + q0.y) + (q1.x + q1.y));
            float l01 = 0.25f * ((q0.z + q0.w) + (q1.z + q1.w));
            float l10 = 0.25f * ((q2.x + q2.y) + (q3.x + q3.y));
            float l11 = 0.25f * ((q2.z + q2.w) + (q3.z + q3.w));

            int r1 = (y0 >> 1) + 2 * i;
            int c1 = (x0 >> 1) + 2 * j;
            *(float2*)(d1 + (size_t)r1 * 256 + c1)       = make_float2(l00, l01);
            *(float2*)(d1 + (size_t)(r1 + 1) * 256 + c1) = make_float2(l10, l11);

            float v2 = 0.25f * ((l00 + l01) + (l10 + l11));
            d2[(size_t)((y0 >> 2) + i) * 128 + (x0 >> 2) + j] = v2;
            sm2[img * 256 + i * 16 + j] = v2;
        }
        __syncthreads();

        if (t < 128) {
            int img = t >> 6, id = t & 63;
            int i3 = id >> 3, j3 = id & 7;
            const float* s = sm2 + img * 256;
            float v3 = 0.25f * ((s[(2*i3)*16 + 2*j3]   + s[(2*i3)*16 + 2*j3 + 1]) +
                                (s[(2*i3+1)*16 + 2*j3] + s[(2*i3+1)*16 + 2*j3 + 1]));
            float* d3 = (img ? b3 : a3) + (size_t)plane * 64 * 64;
            d3[(size_t)((y0 >> 3) + i3) * 64 + (x0 >> 3) + j3] = v3;
            sm3[img * 64 + i3 * 8 + j3] = v3;
        }
        __syncthreads();

        if (t < 32) {
            int img = t >> 4, id = t & 15;
            int i4 = id >> 2, j4 = id & 3;
            const float* s = sm3 + img * 64;
            float v4 = 0.25f * ((s[(2*i4)*8 + 2*j4]   + s[(2*i4)*8 + 2*j4 + 1]) +
                                (s[(2*i4+1)*8 + 2*j4] + s[(2*i4+1)*8 + 2*j4 + 1]));
            float* d4 = (img ? b4 : a4) + (size_t)plane * 32 * 32;
            d4[(size_t)((y0 >> 4) + i4) * 32 + (x0 >> 4) + j4] = v4;
        }
        return;
    }

    // ---- L0 ssim tile ----
    const int rel = bid - 3072;
    const int plane = rel >> 8;
    const int rem = rel & 255;
    const int x0 = (rem & 15) << 5;
    const int y0 = (rem >> 4) << 5;

    ssim_tile(img1 + (size_t)plane * 512 * 512,
              img2 + (size_t)plane * 512 * 512,
              x0, y0, 512, 512, 0,
              s_uv, h4, red_s, red_c);
}

// ---------------------------------------------------------------------------
// Launch 2: levels 1-4 (4080 blocks) + finalize folded into the last block.
// ---------------------------------------------------------------------------
__global__ void __launch_bounds__(NT, 6)
ssim_rest_kernel(const float* __restrict__ a1, const float* __restrict__ b1,
                 const float* __restrict__ a2, const float* __restrict__ b2,
                 const float* __restrict__ a3, const float* __restrict__ b3,
                 const float* __restrict__ a4, const float* __restrict__ b4,
                 float* __restrict__ out)
{
    __shared__ __align__(16) float2 s_uv[INH * INWP];
    __shared__ __align__(16) float4 h4[INH * TW];
    __shared__ float red_s[NT / 32], red_c[NT / 32];
    __shared__ int s_last;

    const int bid = blockIdx.x;
    int level, base;
    if (bid < 3072)      { level = 1; base = 0;    }
    else if (bid < 3840) { level = 2; base = 3072; }
    else if (bid < 4032) { level = 3; base = 3840; }
    else                 { level = 4; base = 4032; }
    const int side = 512 >> level;
    const int lw   = 4 - level;
    const int rel  = bid - base;
    const int plane = rel >> (2 * lw);
    const int rem   = rel & ((1 << (2 * lw)) - 1);
    const int x0 = (rem & ((1 << lw) - 1)) << 5;
    const int y0 = (rem >> lw) << 5;

    const float* img1 = (level == 1) ? a1 : (level == 2) ? a2 :
                        (level == 3) ? a3 : a4;
    const float* img2 = (level == 1) ? b1 : (level == 2) ? b2 :
                        (level == 3) ? b3 : b4;

    ssim_tile(img1 + (size_t)plane * side * side,
              img2 + (size_t)plane * side * side,
              x0, y0, side, side, level,
              s_uv, h4, red_s, red_c);

    // completion protocol: last block computes the final scalar
    const int t = threadIdx.x;
    if (t == 0) {
        __threadfence();
        unsigned int old = atomicAdd(&g_done, 1u);
        s_last = (old == 4079u);
    }
    __syncthreads();
    if (s_last) {
        if (t < 32) {
            __threadfence();
            float term = 0.f;
            if (t < 5) {
                const float w[5] = {0.0448f, 0.2856f, 0.3001f, 0.2363f, 0.1333f};
                int sd = 512 >> t;
                double cnt = (double)NPLANES * sd * sd;
                double v = (t < 4) ? (g_sums[2 * t + 1] / cnt)
                                   : (g_sums[2 * t] / cnt);
                term = w[t] * __logf((float)v);
            }
            #pragma unroll
            for (int o = 16; o > 0; o >>= 1)
                term += __shfl_xor_sync(0xFFFFFFFFu, term, o);
            if (t == 0) {
                out[0] = __expf(term);
                g_done = 0;   // reset for next graph replay
            }
        }
    }
}

extern "C" void kernel_launch(void* const* d_in, const int* in_sizes, int n_in,
                              void* d_out, int out_size)
{
    const float* img1 = (const float*)d_in[0];
    const float* img2 = (const float*)d_in[1];
    float* out = (float*)d_out;

    float *scr1 = nullptr, *scr2 = nullptr;
    cudaGetSymbolAddress((void**)&scr1, g_scr1);
    cudaGetSymbolAddress((void**)&scr2, g_scr2);
    void* sums_ptr = nullptr;
    cudaGetSymbolAddress(&sums_ptr, g_sums);

    float* a1 = scr1 + OFF_L1;  float* b1 = scr2 + OFF_L1;
    float* a2 = scr1 + OFF_L2;  float* b2 = scr2 + OFF_L2;
    float* a3 = scr1 + OFF_L3;  float* b3 = scr2 + OFF_L3;
    float* a4 = scr1 + OFF_L4;  float* b4 = scr2 + OFF_L4;

    cudaMemsetAsync(sums_ptr, 0, 10 * sizeof(double));

    fused_l0_kernel<<<15360, NT>>>(img1, img2, a1, b1, a2, b2, a3, b3, a4, b4);
    ssim_rest_kernel<<<4080, NT>>>(a1, b1, a2, b2, a3, b3, a4, b4, out);
}

// round 16
// speedup vs baseline: 1.0743x; 1.0743x over previous
#include <cuda_runtime.h>
#include <math.h>

// ---------------------------------------------------------------------------
// MS-SSIM, 5 levels, [16,3,512,512] f32.  (R16: 2 kernels, zero re-reads)
//   0) memsetAsync g_sums = 0
//   1) ssim_l0 (12288 blk): L0 ssim + FULL pyramid fused (L1,L2,L3,L4 all
//      pooled from the already-staged 32x32 tile; no separate pyramid pass)
//   2) ssim_rest (4080 blk, levels 1-4) + finalize folded into last block
// Tile core: u=x+y / v=x-y, separable 11-tap blur, k-outer, XOR swizzles.
// ---------------------------------------------------------------------------

#define NPLANES 48
#define HALO 5
#define TW 32
#define TH 32
#define INW 42
#define INWP 44        // float2 units per row (352B)
#define INH 42
#define NT 256

#define G0 0.001028380f
#define G1 0.007598758f
#define G2 0.036000770f
#define G3 0.109360700f
#define G4 0.213005550f
#define G5 0.266011740f

__device__ __forceinline__ float gw(int k) {
    switch (k) {
        case 0: case 10: return G0;
        case 1: case 9:  return G1;
        case 2: case 8:  return G2;
        case 3: case 7:  return G3;
        case 4: case 6:  return G4;
        default:         return G5;
    }
}

__device__ __forceinline__ int swzg(int g) { return g ^ ((g >> 3) & 1); }
__device__ __forceinline__ int suv_idx(int r, int c) {
    int g = swzg(c >> 1);
    return r * INWP + (g << 1) + (c & 1);
}
__device__ __forceinline__ int swzc(int col) { return col ^ (col >> 2); }

#define C1F 0.0001f
#define C2F 0.0009f

__device__ double g_sums[10];
__device__ unsigned int g_done = 0;

#define OFF_L1 0
#define OFF_L2 3145728
#define OFF_L3 3932160
#define OFF_L4 4128768
#define SCR_TOTAL 4177920
__device__ float g_scr1[SCR_TOTAL];
__device__ float g_scr2[SCR_TOTAL];

// ---------------------------------------------------------------------------
// Core ssim tile. If DO_POOL, pools the staged interior down 4 levels,
// using the (pre-h-pass) h4 buffer as scratch.
// ---------------------------------------------------------------------------
template<bool DO_POOL>
__device__ __forceinline__ void ssim_tile(
    const float* __restrict__ p1, const float* __restrict__ p2,
    int plane, int x0, int y0, int H, int W, int level,
    float2* s_uv, float4* h4, float* red_s, float* red_c,
    float* a1, float* b1, float* a2, float* b2,
    float* a3, float* b3, float* a4, float* b4)
{
    const int t = threadIdx.x;

    const bool interior = (x0 >= HALO) && (y0 >= HALO) &&
                          (x0 + TW + HALO <= W) && (y0 + TH + HALO <= H);
    if (interior) {
        #pragma unroll
        for (int i = 0; i < 7; i++) {
            int idx = t + i * NT;
            if (idx < INH * INW) {
                int r = idx / INW, c = idx - r * INW;
                int gi = (y0 + r - HALO) * W + (x0 + c - HALO);
                float a = __ldg(p1 + gi);
                float b = __ldg(p2 + gi);
                s_uv[suv_idx(r, c)] = make_float2(a + b, a - b);
            }
        }
    } else {
        #pragma unroll
        for (int i = 0; i < 7; i++) {
            int idx = t + i * NT;
            if (idx < INH * INW) {
                int r = idx / INW, c = idx - r * INW;
                int gy = y0 + r - HALO;
                int gx = x0 + c - HALO;
                float a = 0.f, b = 0.f;
                if (gy >= 0 && gy < H && gx >= 0 && gx < W) {
                    int gi = gy * W + gx;
                    a = __ldg(p1 + gi);
                    b = __ldg(p2 + gi);
                }
                s_uv[suv_idx(r, c)] = make_float2(a + b, a - b);
            }
        }
    }
    __syncthreads();

    if (DO_POOL) {
        // scratch inside h4 (unused until h-pass)
        float* pu  = (float*)h4;          // 256
        float* pv  = (float*)h4 + 256;    // 256
        float* pu2 = (float*)h4 + 512;    // 64
        float* pv2 = (float*)h4 + 576;    // 64
        float* pu3 = (float*)h4 + 640;    // 16
        float* pv3 = (float*)h4 + 656;    // 16

        // L1: 16x16, one per thread
        {
            int i = t >> 4, j = t & 15;
            int r0 = HALO + 2 * i, c0 = HALO + 2 * j;
            float2 q00 = s_uv[suv_idx(r0, c0)];
            float2 q01 = s_uv[suv_idx(r0, c0 + 1)];
            float2 q10 = s_uv[suv_idx(r0 + 1, c0)];
            float2 q11 = s_uv[suv_idx(r0 + 1, c0 + 1)];
            float u1 = 0.25f * ((q00.x + q01.x) + (q10.x + q11.x));
            float v1 = 0.25f * ((q00.y + q01.y) + (q10.y + q11.y));
            size_t oi = (size_t)plane * (256 * 256) + ((y0 >> 1) + i) * 256 + (x0 >> 1) + j;
            a1[oi] = 0.5f * (u1 + v1);
            b1[oi] = 0.5f * (u1 - v1);
            pu[t] = u1; pv[t] = v1;
        }
        __syncthreads();

        // L2: 8x8
        if (t < 64) {
            int i = t >> 3, j = t & 7;
            int b0 = (2 * i) * 16 + 2 * j;
            float u2 = 0.25f * ((pu[b0] + pu[b0 + 1]) + (pu[b0 + 16] + pu[b0 + 17]));
            float v2 = 0.25f * ((pv[b0] + pv[b0 + 1]) + (pv[b0 + 16] + pv[b0 + 17]));
            size_t oi = (size_t)plane * (128 * 128) + ((y0 >> 2) + i) * 128 + (x0 >> 2) + j;
            a2[oi] = 0.5f * (u2 + v2);
            b2[oi] = 0.5f * (u2 - v2);
            pu2[t] = u2; pv2[t] = v2;
        }
        __syncthreads();

        // L3: 4x4
        if (t < 16) {
            int i = t >> 2, j = t & 3;
            int b0 = (2 * i) * 8 + 2 * j;
            float u3 = 0.25f * ((pu2[b0] + pu2[b0 + 1]) + (pu2[b0 + 8] + pu2[b0 + 9]));
            float v3 = 0.25f * ((pv2[b0] + pv2[b0 + 1]) + (pv2[b0 + 8] + pv2[b0 + 9]));
            size_t oi = (size_t)plane * (64 * 64) + ((y0 >> 3) + i) * 64 + (x0 >> 3) + j;
            a3[oi] = 0.5f * (u3 + v3);
            b3[oi] = 0.5f * (u3 - v3);
            pu3[t] = u3; pv3[t] = v3;
        }
        __syncthreads();

        // L4: 2x2
        if (t < 4) {
            int i = t >> 1, j = t & 1;
            int b0 = (2 * i) * 4 + 2 * j;
            float u4 = 0.25f * ((pu3[b0] + pu3[b0 + 1]) + (pu3[b0 + 4] + pu3[b0 + 5]));
            float v4 = 0.25f * ((pv3[b0] + pv3[b0 + 1]) + (pv3[b0 + 4] + pv3[b0 + 5]));
            size_t oi = (size_t)plane * (32 * 32) + ((y0 >> 4) + i) * 32 + (x0 >> 4) + j;
            a4[oi] = 0.5f * (u4 + v4);
            b4[oi] = 0.5f * (u4 - v4);
        }
        __syncthreads();   // h4 scratch reads done before h-pass overwrites
    }

    // horizontal pass: 42 rows x 8 groups of 4 cols = 336 tasks
    for (int task = t; task < INH * 8; task += NT) {
        const int r     = task >> 3;
        const int jgrp  = task & 7;
        const int cc    = jgrp << 2;
        const int gbase = jgrp << 1;
        const float4* s_uv4 = (const float4*)s_uv;
        const int rowb = r * (INWP >> 1);

        float aU[4] = {0,0,0,0}, aV[4] = {0,0,0,0};
        float aP[4] = {0,0,0,0}, aQ[4] = {0,0,0,0};

        #pragma unroll
        for (int kk = 0; kk < 7; kk++) {
            float4 q = s_uv4[rowb + swzg(gbase + kk)];
            #pragma unroll
            for (int h = 0; h < 2; h++) {
                const int k = 2 * kk + h;
                float u = h ? q.z : q.x;
                float v = h ? q.w : q.y;
                float uu = u * u;
                float vv = v * v;
                #pragma unroll
                for (int j = 0; j < 4; j++) {
                    const int ki = k - j;
                    if (ki >= 0 && ki <= 10) {
                        const float w = gw(ki);
                        aU[j] = fmaf(w, u,  aU[j]);
                        aV[j] = fmaf(w, v,  aV[j]);
                        aP[j] = fmaf(w, uu, aP[j]);
                        aQ[j] = fmaf(w, vv, aQ[j]);
                    }
                }
            }
        }
        #pragma unroll
        for (int j = 0; j < 4; j++)
            h4[r * TW + ((cc + j) ^ jgrp)] = make_float4(aU[j], aV[j], aP[j], aQ[j]);
    }
    __syncthreads();

    // vertical pass + epilogue: 256 tasks, 4 output rows each
    float lssim = 0.f, lcs = 0.f;
    {
        const int tx  = t & 31;
        const int txs = swzc(tx);
        const int rbase = (t >> 5) * 4;

        float aU[4] = {0,0,0,0}, aV[4] = {0,0,0,0};
        float aP[4] = {0,0,0,0}, aQ[4] = {0,0,0,0};
        #pragma unroll
        for (int k = 0; k < 14; k++) {
            float4 hv = h4[(rbase + k) * TW + txs];
            #pragma unroll
            for (int j = 0; j < 4; j++) {
                const int ki = k - j;
                if (ki >= 0 && ki <= 10) {
                    const float w = gw(ki);
                    aU[j] = fmaf(w, hv.x, aU[j]);
                    aV[j] = fmaf(w, hv.y, aV[j]);
                    aP[j] = fmaf(w, hv.z, aP[j]);
                    aQ[j] = fmaf(w, hv.w, aQ[j]);
                }
            }
        }

        #pragma unroll
        for (int j = 0; j < 4; j++) {
            float A = aU[j] * aU[j];
            float B = aV[j] * aV[j];
            float P = aP[j], Q = aQ[j];
            float num_l = 0.5f * (A - B) + C1F;
            float den_l = 0.5f * (A + B) + C1F;
            float num_c = 0.5f * ((P - Q) - (A - B)) + C2F;
            float den_c = 0.5f * ((P + Q) - (A + B)) + C2F;
            float cs = __fdividef(num_c, den_c);
            lssim += __fdividef(num_l, den_l) * cs;
            lcs   += cs;
        }

        #pragma unroll
        for (int o = 16; o > 0; o >>= 1) {
            lssim += __shfl_xor_sync(0xFFFFFFFFu, lssim, o);
            lcs   += __shfl_xor_sync(0xFFFFFFFFu, lcs,   o);
        }
        if (tx == 0) { red_s[t >> 5] = lssim; red_c[t >> 5] = lcs; }
    }
    __syncthreads();
    if (t == 0) {
        float S = 0.f, Cc = 0.f;
        #pragma unroll
        for (int i = 0; i < NT / 32; i++) { S += red_s[i]; Cc += red_c[i]; }
        atomicAdd(&g_sums[2 * level],     (double)S);
        atomicAdd(&g_sums[2 * level + 1], (double)Cc);
    }
}

// ---- Launch 1: L0 ssim + full fused pyramid. grid (16,16,48). ----
__global__ void __launch_bounds__(NT, 6)
ssim_l0_kernel(const float* __restrict__ img1, const float* __restrict__ img2,
               float* __restrict__ a1, float* __restrict__ b1,
               float* __restrict__ a2, float* __restrict__ b2,
               float* __restrict__ a3, float* __restrict__ b3,
               float* __restrict__ a4, float* __restrict__ b4)
{
    __shared__ __align__(16) float2 s_uv[INH * INWP];
    __shared__ __align__(16) float4 h4[INH * TW];
    __shared__ float red_s[NT / 32], red_c[NT / 32];

    const int plane = blockIdx.z;
    ssim_tile<true>(img1 + (size_t)plane * 512 * 512,
                    img2 + (size_t)plane * 512 * 512,
                    plane, blockIdx.x * TW, blockIdx.y * TH, 512, 512, 0,
                    s_uv, h4, red_s, red_c,
                    a1, b1, a2, b2, a3, b3, a4, b4);
}

// ---- Launch 2: levels 1-4 (4080 blocks) + finalize in last block ----
__global__ void __launch_bounds__(NT, 6)
ssim_rest_kernel(const float* __restrict__ a1, const float* __restrict__ b1,
                 const float* __restrict__ a2, const float* __restrict__ b2,
                 const float* __restrict__ a3, const float* __restrict__ b3,
                 const float* __restrict__ a4, const float* __restrict__ b4,
                 float* __restrict__ out)
{
    __shared__ __align__(16) float2 s_uv[INH * INWP];
    __shared__ __align__(16) float4 h4[INH * TW];
    __shared__ float red_s[NT / 32], red_c[NT / 32];
    __shared__ int s_last;

    const int bid = blockIdx.x;
    int level, base;
    if (bid < 3072)      { level = 1; base = 0;    }
    else if (bid < 3840) { level = 2; base = 3072; }
    else if (bid < 4032) { level = 3; base = 3840; }
    else                 { level = 4; base = 4032; }
    const int side = 512 >> level;
    const int lw   = 4 - level;
    const int rel  = bid - base;
    const int plane = rel >> (2 * lw);
    const int rem   = rel & ((1 << (2 * lw)) - 1);
    const int x0 = (rem & ((1 << lw) - 1)) << 5;
    const int y0 = (rem >> lw) << 5;

    const float* img1 = (level == 1) ? a1 : (level == 2) ? a2 :
                        (level == 3) ? a3 : a4;
    const float* img2 = (level == 1) ? b1 : (level == 2) ? b2 :
                        (level == 3) ? b3 : b4;

    ssim_tile<false>(img1 + (size_t)plane * side * side,
                     img2 + (size_t)plane * side * side,
                     plane, x0, y0, side, side, level,
                     s_uv, h4, red_s, red_c,
                     nullptr, nullptr, nullptr, nullptr,
                     nullptr, nullptr, nullptr, nullptr);

    // completion protocol: last block computes the final scalar
    const int t = threadIdx.x;
    if (t == 0) {
        __threadfence();
        unsigned int old = atomicAdd(&g_done, 1u);
        s_last = (old == 4079u);
    }
    __syncthreads();
    if (s_last) {
        if (t < 32) {
            __threadfence();
            float term = 0.f;
            if (t < 5) {
                const float w[5] = {0.0448f, 0.2856f, 0.3001f, 0.2363f, 0.1333f};
                int sd = 512 >> t;
                double cnt = (double)NPLANES * sd * sd;
                double v = (t < 4) ? (g_sums[2 * t + 1] / cnt)
                                   : (g_sums[2 * t] / cnt);
                term = w[t] * __logf((float)v);
            }
            #pragma unroll
            for (int o = 16; o > 0; o >>= 1)
                term += __shfl_xor_sync(0xFFFFFFFFu, term, o);
            if (t == 0) {
                out[0] = __expf(term);
                g_done = 0;   // reset for next graph replay
            }
        }
    }
}

extern "C" void kernel_launch(void* const* d_in, const int* in_sizes, int n_in,
                              void* d_out, int out_size)
{
    const float* img1 = (const float*)d_in[0];
    const float* img2 = (const float*)d_in[1];
    float* out = (float*)d_out;

    float *scr1 = nullptr, *scr2 = nullptr;
    cudaGetSymbolAddress((void**)&scr1, g_scr1);
    cudaGetSymbolAddress((void**)&scr2, g_scr2);
    void* sums_ptr = nullptr;
    cudaGetSymbolAddress(&sums_ptr, g_sums);

    float* a1 = scr1 + OFF_L1;  float* b1 = scr2 + OFF_L1;
    float* a2 = scr1 + OFF_L2;  float* b2 = scr2 + OFF_L2;
    float* a3 = scr1 + OFF_L3;  float* b3 = scr2 + OFF_L3;
    float* a4 = scr1 + OFF_L4;  float* b4 = scr2 + OFF_L4;

    cudaMemsetAsync(sums_ptr, 0, 10 * sizeof(double));

    ssim_l0_kernel<<<dim3(16, 16, NPLANES), NT>>>(
        img1, img2, a1, b1, a2, b2, a3, b3, a4, b4);
    ssim_rest_kernel<<<4080, NT>>>(a1, b1, a2, b2, a3, b3, a4, b4, out);
}

// round 17
// speedup vs baseline: 1.0869x; 1.0118x over previous
#include <cuda_runtime.h>
#include <math.h>

// ---------------------------------------------------------------------------
// MS-SSIM, 5 levels, [16,3,512,512] f32.  (R17 = R14 + finalize fold)
//   0) memsetAsync g_sums = 0
//   1) ssim_l0 (12288 blk): L0 ssim + fused single-level pool -> L1
//   2) pyramid2 (768 blk): L2/L3/L4 from L1 (~3us)
//   3) ssim_rest (4080 blk, levels 1-4) + finalize folded into last block
// Tile core: u=x+y / v=x-y, separable 11-tap blur, k-outer, XOR swizzles.
// ---------------------------------------------------------------------------

#define NPLANES 48
#define HALO 5
#define TW 32
#define TH 32
#define INW 42
#define INWP 44        // float2 units per row (352B)
#define INH 42
#define NT 256

#define G0 0.001028380f
#define G1 0.007598758f
#define G2 0.036000770f
#define G3 0.109360700f
#define G4 0.213005550f
#define G5 0.266011740f

__device__ __forceinline__ float gw(int k) {
    switch (k) {
        case 0: case 10: return G0;
        case 1: case 9:  return G1;
        case 2: case 8:  return G2;
        case 3: case 7:  return G3;
        case 4: case 6:  return G4;
        default:         return G5;
    }
}

__device__ __forceinline__ int swzg(int g) { return g ^ ((g >> 3) & 1); }
__device__ __forceinline__ int suv_idx(int r, int c) {
    int g = swzg(c >> 1);
    return r * INWP + (g << 1) + (c & 1);
}
__device__ __forceinline__ int swzc(int col) { return col ^ (col >> 2); }

#define C1F 0.0001f
#define C2F 0.0009f

__device__ double g_sums[10];
__device__ unsigned int g_done = 0;

#define OFF_L1 0
#define OFF_L2 3145728
#define OFF_L3 3932160
#define OFF_L4 4128768
#define SCR_TOTAL 4177920
__device__ float g_scr1[SCR_TOTAL];
__device__ float g_scr2[SCR_TOTAL];

// ---------------------------------------------------------------------------
// Shared ssim tile routine; optional single-level fused pool (all threads).
// ---------------------------------------------------------------------------
__device__ __forceinline__ void ssim_tile(
    const float* __restrict__ p1, const float* __restrict__ p2,
    float* __restrict__ pool1, float* __restrict__ pool2,   // may be null
    int plane, int x0, int y0, int H, int W, int level,
    float2* s_uv, float4* h4, float* red_s, float* red_c)
{
    const int t = threadIdx.x;

    const bool interior = (x0 >= HALO) && (y0 >= HALO) &&
                          (x0 + TW + HALO <= W) && (y0 + TH + HALO <= H);
    if (interior) {
        #pragma unroll
        for (int i = 0; i < 7; i++) {
            int idx = t + i * NT;
            if (idx < INH * INW) {
                int r = idx / INW, c = idx - r * INW;
                int gi = (y0 + r - HALO) * W + (x0 + c - HALO);
                float a = __ldg(p1 + gi);
                float b = __ldg(p2 + gi);
                s_uv[suv_idx(r, c)] = make_float2(a + b, a - b);
            }
        }
    } else {
        #pragma unroll
        for (int i = 0; i < 7; i++) {
            int idx = t + i * NT;
            if (idx < INH * INW) {
                int r = idx / INW, c = idx - r * INW;
                int gy = y0 + r - HALO;
                int gx = x0 + c - HALO;
                float a = 0.f, b = 0.f;
                if (gy >= 0 && gy < H && gx >= 0 && gx < W) {
                    int gi = gy * W + gx;
                    a = __ldg(p1 + gi);
                    b = __ldg(p2 + gi);
                }
                s_uv[suv_idx(r, c)] = make_float2(a + b, a - b);
            }
        }
    }
    __syncthreads();

    // fused single-level 2x2 pool of interior (32x32 -> 16x16), all threads
    if (pool1) {
        int i = t >> 4, j = t & 15;
        int r0 = HALO + 2 * i, c0 = HALO + 2 * j;
        float2 q00 = s_uv[suv_idx(r0, c0)];
        float2 q01 = s_uv[suv_idx(r0, c0 + 1)];
        float2 q10 = s_uv[suv_idx(r0 + 1, c0)];
        float2 q11 = s_uv[suv_idx(r0 + 1, c0 + 1)];
        float su = (q00.x + q01.x) + (q10.x + q11.x);
        float sv = (q00.y + q01.y) + (q10.y + q11.y);
        int W2 = W >> 1;
        size_t oi = (size_t)plane * (W2 * (H >> 1)) + ((y0 >> 1) + i) * W2 + (x0 >> 1) + j;
        pool1[oi] = 0.125f * (su + sv);
        pool2[oi] = 0.125f * (su - sv);
    }

    // horizontal pass: 42 rows x 8 groups of 4 cols = 336 tasks
    for (int task = t; task < INH * 8; task += NT) {
        const int r     = task >> 3;
        const int jgrp  = task & 7;
        const int cc    = jgrp << 2;
        const int gbase = jgrp << 1;
        const float4* s_uv4 = (const float4*)s_uv;
        const int rowb = r * (INWP >> 1);

        float aU[4] = {0,0,0,0}, aV[4] = {0,0,0,0};
        float aP[4] = {0,0,0,0}, aQ[4] = {0,0,0,0};

        #pragma unroll
        for (int kk = 0; kk < 7; kk++) {
            float4 q = s_uv4[rowb + swzg(gbase + kk)];
            #pragma unroll
            for (int h = 0; h < 2; h++) {
                const int k = 2 * kk + h;
                float u = h ? q.z : q.x;
                float v = h ? q.w : q.y;
                float uu = u * u;
                float vv = v * v;
                #pragma unroll
                for (int j = 0; j < 4; j++) {
                    const int ki = k - j;
                    if (ki >= 0 && ki <= 10) {
                        const float w = gw(ki);
                        aU[j] = fmaf(w, u,  aU[j]);
                        aV[j] = fmaf(w, v,  aV[j]);
                        aP[j] = fmaf(w, uu, aP[j]);
                        aQ[j] = fmaf(w, vv, aQ[j]);
                    }
                }
            }
        }
        #pragma unroll
        for (int j = 0; j < 4; j++)
            h4[r * TW + ((cc + j) ^ jgrp)] = make_float4(aU[j], aV[j], aP[j], aQ[j]);
    }
    __syncthreads();

    // vertical pass + epilogue: 256 tasks, 4 output rows each
    float lssim = 0.f, lcs = 0.f;
    {
        const int tx  = t & 31;
        const int txs = swzc(tx);
        const int rbase = (t >> 5) * 4;

        float aU[4] = {0,0,0,0}, aV[4] = {0,0,0,0};
        float aP[4] = {0,0,0,0}, aQ[4] = {0,0,0,0};
        #pragma unroll
        for (int k = 0; k < 14; k++) {
            float4 hv = h4[(rbase + k) * TW + txs];
            #pragma unroll
            for (int j = 0; j < 4; j++) {
                const int ki = k - j;
                if (ki >= 0 && ki <= 10) {
                    const float w = gw(ki);
                    aU[j] = fmaf(w, hv.x, aU[j]);
                    aV[j] = fmaf(w, hv.y, aV[j]);
                    aP[j] = fmaf(w, hv.z, aP[j]);
                    aQ[j] = fmaf(w, hv.w, aQ[j]);
                }
            }
        }

        #pragma unroll
        for (int j = 0; j < 4; j++) {
            float A = aU[j] * aU[j];
            float B = aV[j] * aV[j];
            float P = aP[j], Q = aQ[j];
            float num_l = 0.5f * (A - B) + C1F;
            float den_l = 0.5f * (A + B) + C1F;
            float num_c = 0.5f * ((P - Q) - (A - B)) + C2F;
            float den_c = 0.5f * ((P + Q) - (A + B)) + C2F;
            float cs = __fdividef(num_c, den_c);
            lssim += __fdividef(num_l, den_l) * cs;
            lcs   += cs;
        }

        #pragma unroll
        for (int o = 16; o > 0; o >>= 1) {
            lssim += __shfl_xor_sync(0xFFFFFFFFu, lssim, o);
            lcs   += __shfl_xor_sync(0xFFFFFFFFu, lcs,   o);
        }
        if (tx == 0) { red_s[t >> 5] = lssim; red_c[t >> 5] = lcs; }
    }
    __syncthreads();
    if (t == 0) {
        float S = 0.f, Cc = 0.f;
        #pragma unroll
        for (int i = 0; i < NT / 32; i++) { S += red_s[i]; Cc += red_c[i]; }
        atomicAdd(&g_sums[2 * level],     (double)S);
        atomicAdd(&g_sums[2 * level + 1], (double)Cc);
    }
}

// ---- Launch 1: L0 ssim + fused pool -> L1. grid (16,16,48). ----
__global__ void __launch_bounds__(NT, 6)
ssim_l0_kernel(const float* __restrict__ img1, const float* __restrict__ img2,
               float* __restrict__ pool1, float* __restrict__ pool2)
{
    __shared__ __align__(16) float2 s_uv[INH * INWP];
    __shared__ __align__(16) float4 h4[INH * TW];
    __shared__ float red_s[NT / 32], red_c[NT / 32];

    const int plane = blockIdx.z;
    ssim_tile(img1 + (size_t)plane * 512 * 512,
              img2 + (size_t)plane * 512 * 512,
              pool1, pool2, plane,
              blockIdx.x * TW, blockIdx.y * TH, 512, 512, 0,
              s_uv, h4, red_s, red_c);
}

// ---- Launch 2: pyramid L2/L3/L4 from L1. grid (4,4,48), 256 thr. ----
__global__ void __launch_bounds__(256)
pyramid2_kernel(const float* __restrict__ i1, const float* __restrict__ i2,
                float* __restrict__ a2, float* __restrict__ b2,
                float* __restrict__ a3, float* __restrict__ b3,
                float* __restrict__ a4, float* __restrict__ b4)
{
    __shared__ float sm3[2][256];

    const int t = threadIdx.x;
    const int i = t >> 4, j = t & 15;
    const int plane = blockIdx.z;
    const int x0 = blockIdx.x * 64, y0 = blockIdx.y * 64;   // L1 coords

    #pragma unroll
    for (int img = 0; img < 2; img++) {
        const float* p = (img ? i2 : i1) + (size_t)plane * 256 * 256;
        float* d2 = (img ? b2 : a2) + (size_t)plane * 128 * 128;
        float* d3 = (img ? b3 : a3) + (size_t)plane * 64 * 64;

        const int ry = y0 + 4 * i;
        const int cx = x0 + 4 * j;
        float4 q0 = *(const float4*)(p + (size_t)(ry + 0) * 256 + cx);
        float4 q1 = *(const float4*)(p + (size_t)(ry + 1) * 256 + cx);
        float4 q2 = *(const float4*)(p + (size_t)(ry + 2) * 256 + cx);
        float4 q3 = *(const float4*)(p + (size_t)(ry + 3) * 256 + cx);

        float l00 = 0.25f * ((q0.x + q0.y) + (q1.x + q1.y));
        float l01 = 0.25f * ((q0.z + q0.w) + (q1.z + q1.w));
        float l10 = 0.25f * ((q2.x + q2.y) + (q3.x + q3.y));
        float l11 = 0.25f * ((q2.z + q2.w) + (q3.z + q3.w));

        int r2 = (y0 >> 1) + 2 * i;
        int c2 = (x0 >> 1) + 2 * j;
        *(float2*)(d2 + (size_t)r2 * 128 + c2)       = make_float2(l00, l01);
        *(float2*)(d2 + (size_t)(r2 + 1) * 128 + c2) = make_float2(l10, l11);

        float v3 = 0.25f * ((l00 + l01) + (l10 + l11));
        d3[(size_t)((y0 >> 2) + i) * 64 + (x0 >> 2) + j] = v3;
        sm3[img][i * 16 + j] = v3;
    }
    __syncthreads();

    if (t < 128) {
        int img = t >> 6, id = t & 63;
        int i4 = id >> 3, j4 = id & 7;
        const float* s = sm3[img];
        float v4 = 0.25f * ((s[(2*i4)*16 + 2*j4]   + s[(2*i4)*16 + 2*j4 + 1]) +
                            (s[(2*i4+1)*16 + 2*j4] + s[(2*i4+1)*16 + 2*j4 + 1]));
        float* d4 = (img ? b4 : a4) + (size_t)plane * 32 * 32;
        d4[(size_t)((y0 >> 3) + i4) * 32 + (x0 >> 3) + j4] = v4;
    }
}

// ---- Launch 3: levels 1-4 (4080 blocks) + finalize in last block ----
__global__ void __launch_bounds__(NT, 6)
ssim_rest_kernel(const float* __restrict__ a1, const float* __restrict__ b1,
                 const float* __restrict__ a2, const float* __restrict__ b2,
                 const float* __restrict__ a3, const float* __restrict__ b3,
                 const float* __restrict__ a4, const float* __restrict__ b4,
                 float* __restrict__ out)
{
    __shared__ __align__(16) float2 s_uv[INH * INWP];
    __shared__ __align__(16) float4 h4[INH * TW];
    __shared__ float red_s[NT / 32], red_c[NT / 32];
    __shared__ int s_last;

    const int bid = blockIdx.x;
    int level, base;
    if (bid < 3072)      { level = 1; base = 0;    }
    else if (bid < 3840) { level = 2; base = 3072; }
    else if (bid < 4032) { level = 3; base = 3840; }
    else                 { level = 4; base = 4032; }
    const int side = 512 >> level;
    const int lw   = 4 - level;
    const int rel  = bid - base;
    const int plane = rel >> (2 * lw);
    const int rem   = rel & ((1 << (2 * lw)) - 1);
    const int x0 = (rem & ((1 << lw) - 1)) << 5;
    const int y0 = (rem >> lw) << 5;

    const float* img1 = (level == 1) ? a1 : (level == 2) ? a2 :
                        (level == 3) ? a3 : a4;
    const float* img2 = (level == 1) ? b1 : (level == 2) ? b2 :
                        (level == 3) ? b3 : b4;

    ssim_tile(img1 + (size_t)plane * side * side,
              img2 + (size_t)plane * side * side,
              nullptr, nullptr, plane,
              x0, y0, side, side, level,
              s_uv, h4, red_s, red_c);

    // completion protocol: last block computes the final scalar
    const int t = threadIdx.x;
    if (t == 0) {
        __threadfence();
        unsigned int old = atomicAdd(&g_done, 1u);
        s_last = (old == 4079u);
    }
    __syncthreads();
    if (s_last) {
        if (t < 32) {
            __threadfence();
            float term = 0.f;
            if (t < 5) {
                const float w[5] = {0.0448f, 0.2856f, 0.3001f, 0.2363f, 0.1333f};
                int sd = 512 >> t;
                double cnt = (double)NPLANES * sd * sd;
                double v = (t < 4) ? (g_sums[2 * t + 1] / cnt)
                                   : (g_sums[2 * t] / cnt);
                term = w[t] * __logf((float)v);
            }
            #pragma unroll
            for (int o = 16; o > 0; o >>= 1)
                term += __shfl_xor_sync(0xFFFFFFFFu, term, o);
            if (t == 0) {
                out[0] = __expf(term);
                g_done = 0;   // reset for next graph replay
            }
        }
    }
}

extern "C" void kernel_launch(void* const* d_in, const int* in_sizes, int n_in,
                              void* d_out, int out_size)
{
    const float* img1 = (const float*)d_in[0];
    const float* img2 = (const float*)d_in[1];
    float* out = (float*)d_out;

    float *scr1 = nullptr, *scr2 = nullptr;
    cudaGetSymbolAddress((void**)&scr1, g_scr1);
    cudaGetSymbolAddress((void**)&scr2, g_scr2);
    void* sums_ptr = nullptr;
    cudaGetSymbolAddress(&sums_ptr, g_sums);

    float* a1 = scr1 + OFF_L1;  float* b1 = scr2 + OFF_L1;
    float* a2 = scr1 + OFF_L2;  float* b2 = scr2 + OFF_L2;
    float* a3 = scr1 + OFF_L3;  float* b3 = scr2 + OFF_L3;
    float* a4 = scr1 + OFF_L4;  float* b4 = scr2 + OFF_L4;

    cudaMemsetAsync(sums_ptr, 0, 10 * sizeof(double));

    ssim_l0_kernel<<<dim3(16, 16, NPLANES), NT>>>(img1, img2, a1, b1);
    pyramid2_kernel<<<dim3(4, 4, NPLANES), 256>>>(a1, b1, a2, b2, a3, b3, a4, b4);
    ssim_rest_kernel<<<4080, NT>>>(a1, b1, a2, b2, a3, b3, a4, b4, out);
}